// round 2
// baseline (speedup 1.0000x reference)
#include <cuda_runtime.h>

#define NB 65536
#define XDIM 362
#define NACT 3
#define GS 19

typedef unsigned long long ull;

// ---------- scratch (static __device__, no allocation) ----------
__device__ int   g_cnt[NACT];
__device__ int   g_perm[NACT * NB];
__device__ int   g_ptr[NB];
__device__ float g_att[NB * 6];

// ---------- packed f32x2 helpers ----------
__device__ __forceinline__ ull ffma2(ull a, ull b, ull c) {
    ull d;
    asm("fma.rn.f32x2 %0, %1, %2, %3;" : "=l"(d) : "l"(a), "l"(b), "l"(c));
    return d;
}
__device__ __forceinline__ ull pack2(float lo, float hi) {
    ull d;
    asm("mov.b64 %0, {%1, %2};" : "=l"(d) : "f"(lo), "f"(hi));
    return d;
}
__device__ __forceinline__ void unpack2(ull v, float& lo, float& hi) {
    asm("mov.b64 {%0, %1}, %2;" : "=f"(lo), "=f"(hi) : "l"(v));
}
__device__ __forceinline__ int clampi(int v) { return min(max(v, 1), XDIM - 1); }

// ---------- K1: argmax + copy + gather + action bucketing ----------
__global__ void __launch_bounds__(256) k_prep(const float* __restrict__ x,
                                              const int* __restrict__ act,
                                              float* __restrict__ out) {
    const int warp = threadIdx.x >> 5;
    const int lane = threadIdx.x & 31;
    const int row = blockIdx.x * 8 + warp;

    const float2* __restrict__ xr = (const float2*)(x + (size_t)row * XDIM);
    float2* __restrict__ orow = (float2*)(out + (size_t)row * XDIM);

    float bv = -3.4e38f;
    int bi = 0;
    #pragma unroll
    for (int it = 0; it < 6; ++it) {
        int i = it * 32 + lane;
        if (i < 181) {
            float2 v = xr[i];
            orow[i] = v;  // fused copy of batch_x into out
            int c0 = 2 * i;
            if (v.x > bv) { bv = v.x; bi = c0; }
            if (v.y > bv) { bv = v.y; bi = c0 + 1; }
        }
    }
    #pragma unroll
    for (int off = 16; off; off >>= 1) {
        float ov = __shfl_down_sync(0xffffffffu, bv, off);
        int oi = __shfl_down_sync(0xffffffffu, bi, off);
        if (ov > bv || (ov == bv && oi < bi)) { bv = ov; bi = oi; }
    }
    const int ptr = __shfl_sync(0xffffffffu, bi, 0);

    if (lane < 6) {
        int idx;
        if (lane == 0) idx = 0;
        else if (lane == 1) idx = ptr;
        else if (lane == 2) idx = clampi(ptr - GS);
        else if (lane == 3) idx = clampi(ptr + GS);
        else if (lane == 4) idx = clampi(ptr - 1);
        else idx = clampi(ptr + 1);
        g_att[row * 6 + lane] = x[(size_t)row * XDIM + idx];
    }
    if (lane == 0) {
        g_ptr[row] = ptr;
        int a = act[row];
        int pos = atomicAdd(&g_cnt[a], 1);
        g_perm[a * NB + pos] = row;
    }
}

// ---------- K2: fused MLP, 2 threads per sample ----------
// shared layout (floats); half-split rows: half h occupies [h*52, h*52+50)
#define W2T_OFF 0        // [100][104] transposed chunk of W2
#define W3_OFF 10400     // [100][104] chunk of W3
#define W1_OFF 20800     // [6][104]  (plain, m contiguous)
#define B1_OFF 21424     // [100]
#define B2_OFF 21524     // [400]
#define B3_OFF 21924     // [100]
#define W4_OFF 22024     // [100][6]
#define B4_OFF 22624     // [6]
#define SMEM_FLOATS 22632

extern __shared__ float sm[];

__global__ void __launch_bounds__(256, 1) k_mlp(
    const float* __restrict__ W1, const float* __restrict__ b1,
    const float* __restrict__ W2, const float* __restrict__ b2,
    const float* __restrict__ W3, const float* __restrict__ b3,
    const float* __restrict__ W4, const float* __restrict__ b4,
    float* __restrict__ out)
{
    const int a = blockIdx.y;
    const int cnt = g_cnt[a];
    const int base = blockIdx.x * 128;          // 128 samples per CTA
    if (base >= cnt) return;
    const int tid = threadIdx.x;
    const int half = tid & 1;                   // pair role
    const int hoff50 = half * 50;
    const int hoff52 = half * 52;

    // one-time small weights
    for (int t = tid; t < 600; t += 256)
        sm[W1_OFF + (t / 100) * 104 + (t % 100)] = W1[a * 600 + t];
    for (int t = tid; t < 100; t += 256) sm[B1_OFF + t] = b1[a * 100 + t];
    for (int t = tid; t < 400; t += 256) sm[B2_OFF + t] = b2[a * 400 + t];
    for (int t = tid; t < 100; t += 256) sm[B3_OFF + t] = b3[a * 100 + t];
    for (int t = tid; t < 600; t += 256) sm[W4_OFF + t] = W4[a * 600 + t];
    if (tid < 6) sm[B4_OFF + tid] = b4[a * 6 + tid];
    // chunk 0 of W2 (transposed, half-split) and W3 (half-split)
    for (int t = tid; t < 10000; t += 256) {
        int k = t / 100, j = t % 100;
        int kk = k + (k >= 50 ? 2 : 0);
        sm[W2T_OFF + j * 104 + kk] = W2[a * 40000 + k * 400 + j];
    }
    for (int t = tid; t < 10000; t += 256) {
        int j = t / 100, m = t % 100;
        int mm = m + (m >= 50 ? 2 : 0);
        sm[W3_OFF + j * 104 + mm] = W3[a * 40000 + j * 100 + m];
    }
    __syncthreads();

    const int gidx = base + (tid >> 1);
    const bool active = gidx < cnt;
    const int s = active ? g_perm[a * NB + gidx] : 0;

    // attention values (both pair threads load all 6; kept for scatter)
    float att[6];
    #pragma unroll
    for (int k = 0; k < 6; ++k) att[k] = g_att[s * 6 + k];

    // layer 1: this thread's 50 h1 values (m = hoff50 .. hoff50+49)
    ull h1p[25];
    {
        const ull* sb1 = (const ull*)(sm + B1_OFF + hoff50);
        #pragma unroll
        for (int i = 0; i < 25; ++i) h1p[i] = sb1[i];
        #pragma unroll
        for (int k = 0; k < 6; ++k) {
            ull attp = pack2(att[k], att[k]);
            const ull* w1p = (const ull*)(sm + W1_OFF + k * 104 + hoff50);
            #pragma unroll
            for (int i = 0; i < 25; ++i) h1p[i] = ffma2(attp, w1p[i], h1p[i]);
        }
        #pragma unroll
        for (int i = 0; i < 25; ++i) {
            float lo, hi;
            unpack2(h1p[i], lo, hi);
            h1p[i] = pack2(fmaxf(lo, 0.0f), fmaxf(hi, 0.0f));
        }
    }

    // layer-3 accumulators for this thread's 50 m outputs
    ull acc3[25];
    {
        const ull* sb3 = (const ull*)(sm + B3_OFF + hoff50);
        #pragma unroll
        for (int i = 0; i < 25; ++i) acc3[i] = sb3[i];
    }

    // layers 2+3 fused over j, 4 chunks of 100 j's
    #pragma unroll 1
    for (int c = 0; c < 4; ++c) {
        if (c > 0) {
            __syncthreads();
            for (int t = tid; t < 10000; t += 256) {
                int k = t / 100, j = t % 100;
                int kk = k + (k >= 50 ? 2 : 0);
                sm[W2T_OFF + j * 104 + kk] = W2[a * 40000 + k * 400 + c * 100 + j];
            }
            for (int t = tid; t < 10000; t += 256) {
                int j = t / 100, m = t % 100;
                int mm = m + (m >= 50 ? 2 : 0);
                sm[W3_OFF + j * 104 + mm] = W3[a * 40000 + (c * 100 + j) * 100 + m];
            }
            __syncthreads();
        }
        #pragma unroll 2
        for (int j = 0; j < 100; ++j) {
            // layer-2 partial dot over this thread's k-half
            const float* w2r = sm + W2T_OFF + j * 104 + hoff52;
            ull a0 = 0ull, a1 = 0ull;
            const ulonglong2* w2q = (const ulonglong2*)w2r;
            #pragma unroll
            for (int q = 0; q < 12; ++q) {
                ulonglong2 w = w2q[q];
                a0 = ffma2(h1p[2 * q], w.x, a0);
                a1 = ffma2(h1p[2 * q + 1], w.y, a1);
            }
            a0 = ffma2(h1p[24], ((const ull*)w2r)[24], a0);
            float l0, h0, l1, h1v;
            unpack2(a0, l0, h0);
            unpack2(a1, l1, h1v);
            float part = (l0 + h0) + (l1 + h1v);
            float other = __shfl_xor_sync(0xffffffffu, part, 1);
            float h2 = fmaxf(part + other + sm[B2_OFF + c * 100 + j], 0.0f);
            ull h2p = pack2(h2, h2);
            // layer-3 accumulate over this thread's m-half
            const float* w3r = sm + W3_OFF + j * 104 + hoff52;
            const ulonglong2* w3q = (const ulonglong2*)w3r;
            #pragma unroll
            for (int q = 0; q < 12; ++q) {
                ulonglong2 w = w3q[q];
                acc3[2 * q] = ffma2(h2p, w.x, acc3[2 * q]);
                acc3[2 * q + 1] = ffma2(h2p, w.y, acc3[2 * q + 1]);
            }
            acc3[24] = ffma2(h2p, ((const ull*)w3r)[24], acc3[24]);
        }
    }

    // layer 4: partial over this thread's 50 h3 values, combine across pair
    float p[6];
    #pragma unroll
    for (int o = 0; o < 6; ++o) p[o] = half ? 0.0f : sm[B4_OFF + o];
    #pragma unroll
    for (int q = 0; q < 25; ++q) {
        float h3a, h3b;
        unpack2(acc3[q], h3a, h3b);
        h3a = fmaxf(h3a, 0.0f);
        h3b = fmaxf(h3b, 0.0f);
        const float* w4a = sm + W4_OFF + (hoff50 + 2 * q) * 6;
        #pragma unroll
        for (int o = 0; o < 6; ++o) {
            p[o] = fmaf(h3a, w4a[o], p[o]);
            p[o] = fmaf(h3b, w4a[6 + o], p[o]);
        }
    }
    #pragma unroll
    for (int o = 0; o < 6; ++o) p[o] += __shfl_xor_sync(0xffffffffu, p[o], 1);

    if (!active || half) return;

    // scatter: out[idx_j] = x[idx_j] + pred[j], j ascending (last wins)
    const int ptr = g_ptr[s];
    int idxs[6];
    idxs[0] = 0;
    idxs[1] = ptr;
    idxs[2] = clampi(ptr - GS);
    idxs[3] = clampi(ptr + GS);
    idxs[4] = clampi(ptr - 1);
    idxs[5] = clampi(ptr + 1);
    float* orow = out + (size_t)s * XDIM;
    #pragma unroll
    for (int j = 0; j < 6; ++j) orow[idxs[j]] = att[j] + p[j];
}

// ---------- launch ----------
extern "C" void kernel_launch(void* const* d_in, const int* in_sizes, int n_in,
                              void* d_out, int out_size) {
    const float* x  = (const float*)d_in[0];
    const float* W1 = (const float*)d_in[1];
    const float* b1 = (const float*)d_in[2];
    const float* W2 = (const float*)d_in[3];
    const float* b2 = (const float*)d_in[4];
    const float* W3 = (const float*)d_in[5];
    const float* b3 = (const float*)d_in[6];
    const float* W4 = (const float*)d_in[7];
    const float* b4 = (const float*)d_in[8];
    const int* act  = (const int*)d_in[9];
    float* out = (float*)d_out;

    static void* cnt_addr = nullptr;
    if (!cnt_addr) cudaGetSymbolAddress(&cnt_addr, g_cnt);

    cudaFuncSetAttribute(k_mlp, cudaFuncAttributeMaxDynamicSharedMemorySize,
                         SMEM_FLOATS * (int)sizeof(float));

    cudaMemsetAsync(cnt_addr, 0, NACT * sizeof(int));
    k_prep<<<NB / 8, 256>>>(x, act, out);
    dim3 g2((NB + 127) / 128, NACT);
    k_mlp<<<g2, 256, SMEM_FLOATS * sizeof(float)>>>(W1, b1, W2, b2, W3, b3,
                                                    W4, b4, out);
}

// round 5
// speedup vs baseline: 1.3577x; 1.3577x over previous
#include <cuda_runtime.h>
#include <cstdint>

#define NB 65536
#define XDIM 362
#define NACT 3
#define GS 19

// ---------- scratch ----------
__device__ int   g_cnt[NACT];
__device__ int   g_perm[NACT * NB];
__device__ int   g_ptr[NB];
__device__ float g_att[NB * 6];

__device__ __forceinline__ int clampi(int v) { return min(max(v, 1), XDIM - 1); }

__device__ __forceinline__ uint32_t to_tf32(float f) {
    uint32_t r;
    asm("cvt.rna.tf32.f32 %0, %1;" : "=r"(r) : "f"(f));
    return r;
}
__device__ __forceinline__ float tf32f(float f) {
    return __uint_as_float(to_tf32(f));
}
// D += A(16x8) * B(8x8), tf32 inputs, f32 accum
__device__ __forceinline__ void mma8(float& c0, float& c1, float& c2, float& c3,
                                     uint32_t a0, uint32_t a1, uint32_t a2, uint32_t a3,
                                     uint32_t b0, uint32_t b1) {
    asm volatile(
        "mma.sync.aligned.m16n8k8.row.col.f32.tf32.tf32.f32 "
        "{%0,%1,%2,%3}, {%4,%5,%6,%7}, {%8,%9}, {%0,%1,%2,%3};"
        : "+f"(c0), "+f"(c1), "+f"(c2), "+f"(c3)
        : "r"(a0), "r"(a1), "r"(a2), "r"(a3), "r"(b0), "r"(b1));
}

// ---------- K1: argmax + copy + gather + action bucketing ----------
__global__ void __launch_bounds__(256) k_prep(const float* __restrict__ x,
                                              const int* __restrict__ act,
                                              float* __restrict__ out) {
    const int warp = threadIdx.x >> 5;
    const int lane = threadIdx.x & 31;
    const int row = blockIdx.x * 8 + warp;

    const float2* __restrict__ xr = (const float2*)(x + (size_t)row * XDIM);
    float2* __restrict__ orow = (float2*)(out + (size_t)row * XDIM);

    float bv = -3.4e38f;
    int bi = 0;
    #pragma unroll
    for (int it = 0; it < 6; ++it) {
        int i = it * 32 + lane;
        if (i < 181) {
            float2 v = xr[i];
            orow[i] = v;
            int c0 = 2 * i;
            if (v.x > bv) { bv = v.x; bi = c0; }
            if (v.y > bv) { bv = v.y; bi = c0 + 1; }
        }
    }
    #pragma unroll
    for (int off = 16; off; off >>= 1) {
        float ov = __shfl_down_sync(0xffffffffu, bv, off);
        int oi = __shfl_down_sync(0xffffffffu, bi, off);
        if (ov > bv || (ov == bv && oi < bi)) { bv = ov; bi = oi; }
    }
    const int ptr = __shfl_sync(0xffffffffu, bi, 0);

    if (lane < 6) {
        int idx;
        if (lane == 0) idx = 0;
        else if (lane == 1) idx = ptr;
        else if (lane == 2) idx = clampi(ptr - GS);
        else if (lane == 3) idx = clampi(ptr + GS);
        else if (lane == 4) idx = clampi(ptr - 1);
        else idx = clampi(ptr + 1);
        g_att[row * 6 + lane] = x[(size_t)row * XDIM + idx];
    }
    if (lane == 0) {
        g_ptr[row] = ptr;
        int a = act[row];
        int pos = atomicAdd(&g_cnt[a], 1);
        g_perm[a * NB + pos] = row;
    }
}

// ---------- K2: mma.sync tf32 MLP ----------
// smem float offsets
#define W2C_ 0          // [104 k][104 n] tf32, stride 104
#define W3C_ 10816      // [104 j][104 m] tf32, stride 104
#define HB1_ 21632      // per-warp H1 [32][108]
#define HT_  35456      // per-warp Htmp [32][12]
#define SW1_ 36992      // W1 [6][100]
#define SB1_ 37592
#define SB2_ 37692
#define SB3_ 38092
#define SW4_ 38196      // W4 [100][6]
#define SB4_ 38796
#define SMEMF 38804
#define SMEMB (SMEMF * 4)

__global__ void __launch_bounds__(128, 1) k_mlp(
    const float* __restrict__ W1, const float* __restrict__ b1,
    const float* __restrict__ W2, const float* __restrict__ b2,
    const float* __restrict__ W3, const float* __restrict__ b3,
    const float* __restrict__ W4, const float* __restrict__ b4,
    float* __restrict__ out)
{
    extern __shared__ float sm[];
    const int a = blockIdx.y;
    const int cnt = g_cnt[a];
    const int base = blockIdx.x * 128;
    if (base >= cnt) return;
    const int tid = threadIdx.x;
    const int w = tid >> 5;
    const int lane = tid & 31;
    const int g = lane >> 2;       // groupID (row group)
    const int tig = lane & 3;      // thread in group

    float* __restrict__ Hw = sm + HB1_ + w * (32 * 108);
    float* __restrict__ Ht = sm + HT_ + w * (32 * 12);
    const float* __restrict__ W2g = W2 + a * 40000;
    const float* __restrict__ W3g = W3 + a * 40000;

    // small weights
    for (int t = tid; t < 600; t += 128) sm[SW1_ + t] = W1[a * 600 + t];
    for (int t = tid; t < 100; t += 128) sm[SB1_ + t] = b1[a * 100 + t];
    for (int t = tid; t < 400; t += 128) sm[SB2_ + t] = b2[a * 400 + t];
    for (int t = tid; t < 100; t += 128) sm[SB3_ + t] = b3[a * 100 + t];
    for (int t = tid; t < 600; t += 128) sm[SW4_ + t] = W4[a * 600 + t];
    for (int t = tid; t < 8; t += 128) sm[SB4_ + t] = (t < 6) ? b4[a * 6 + t] : 0.0f;

    // ---- layer 1: one lane = one sample, write tf32 H1 to smem ----
    {
        const int gidx = base + w * 32 + lane;
        const bool act_s = gidx < cnt;
        const int s = g_perm[a * NB + (act_s ? gidx : 0)];
        float att[6];
        #pragma unroll
        for (int k = 0; k < 6; ++k) att[k] = g_att[s * 6 + k];
        for (int m = 0; m < 100; ++m) {
            float acc = sm[SB1_ + m];
            #pragma unroll
            for (int k = 0; k < 6; ++k) acc = fmaf(att[k], sm[SW1_ + k * 100 + m], acc);
            Hw[lane * 108 + m] = tf32f(fmaxf(acc, 0.0f));
        }
        #pragma unroll
        for (int m = 100; m < 104; ++m) Hw[lane * 108 + m] = 0.0f;
    }

    // H3 accumulators: [13 m-tiles][8] (mtile0: c0..c3 rows g/g+8; mtile1: rows g+16/g+24)
    float h3[13][8];
    #pragma unroll
    for (int mt = 0; mt < 13; ++mt)
        #pragma unroll
        for (int q = 0; q < 8; ++q) h3[mt][q] = 0.0f;

    // ---- chunks of 100 j's ----
    #pragma unroll 1
    for (int c = 0; c < 4; ++c) {
        __syncthreads();
        // load W2 chunk (transposed to [k][n]) and W3 chunk ([j][m]) as tf32
        const int cb = c * 100;
        for (int t = tid; t < 10816; t += 128) {
            int k = t / 104, n = t - k * 104;
            bool ok = (k < 100) && (n < 100);
            sm[W2C_ + t] = ok ? tf32f(W2g[k * 400 + cb + n]) : 0.0f;
            sm[W3C_ + t] = ok ? tf32f(W3g[(cb + k) * 100 + n]) : 0.0f;
        }
        __syncthreads();

        #pragma unroll 1
        for (int nt = 0; nt < 13; ++nt) {
            // MMA1: d = H1[32 x 104] x W2c[:, nt*8..nt*8+7]
            float d[8];
            #pragma unroll
            for (int q = 0; q < 8; ++q) d[q] = 0.0f;
            #pragma unroll
            for (int k = 0; k < 13; ++k) {
                const int k0 = k * 8;
                uint32_t a0 = __float_as_uint(Hw[g * 108 + k0 + tig]);
                uint32_t a1 = __float_as_uint(Hw[(g + 8) * 108 + k0 + tig]);
                uint32_t a2 = __float_as_uint(Hw[g * 108 + k0 + tig + 4]);
                uint32_t a3 = __float_as_uint(Hw[(g + 8) * 108 + k0 + tig + 4]);
                uint32_t a4 = __float_as_uint(Hw[(g + 16) * 108 + k0 + tig]);
                uint32_t a5 = __float_as_uint(Hw[(g + 24) * 108 + k0 + tig]);
                uint32_t a6 = __float_as_uint(Hw[(g + 16) * 108 + k0 + tig + 4]);
                uint32_t a7 = __float_as_uint(Hw[(g + 24) * 108 + k0 + tig + 4]);
                uint32_t b0 = __float_as_uint(sm[W2C_ + (k0 + tig) * 104 + nt * 8 + g]);
                uint32_t b1 = __float_as_uint(sm[W2C_ + (k0 + tig + 4) * 104 + nt * 8 + g]);
                mma8(d[0], d[1], d[2], d[3], a0, a1, a2, a3, b0, b1);
                mma8(d[4], d[5], d[6], d[7], a4, a5, a6, a7, b0, b1);
            }
            // bias + relu + tf32, store k=8 slice to Htmp
            {
                const int jl = nt * 8 + 2 * tig;
                float bb0 = 0.0f, bb1 = 0.0f;
                bool okj = jl < 100;
                if (okj) { bb0 = sm[SB2_ + cb + jl]; bb1 = sm[SB2_ + cb + jl + 1]; }
                float v0 = okj ? fmaxf(d[0] + bb0, 0.0f) : 0.0f;
                float v1 = okj ? fmaxf(d[1] + bb1, 0.0f) : 0.0f;
                float v2 = okj ? fmaxf(d[2] + bb0, 0.0f) : 0.0f;
                float v3 = okj ? fmaxf(d[3] + bb1, 0.0f) : 0.0f;
                float v4 = okj ? fmaxf(d[4] + bb0, 0.0f) : 0.0f;
                float v5 = okj ? fmaxf(d[5] + bb1, 0.0f) : 0.0f;
                float v6 = okj ? fmaxf(d[6] + bb0, 0.0f) : 0.0f;
                float v7 = okj ? fmaxf(d[7] + bb1, 0.0f) : 0.0f;
                Ht[g * 12 + 2 * tig] = tf32f(v0);
                Ht[g * 12 + 2 * tig + 1] = tf32f(v1);
                Ht[(g + 8) * 12 + 2 * tig] = tf32f(v2);
                Ht[(g + 8) * 12 + 2 * tig + 1] = tf32f(v3);
                Ht[(g + 16) * 12 + 2 * tig] = tf32f(v4);
                Ht[(g + 16) * 12 + 2 * tig + 1] = tf32f(v5);
                Ht[(g + 24) * 12 + 2 * tig] = tf32f(v6);
                Ht[(g + 24) * 12 + 2 * tig + 1] = tf32f(v7);
            }
            __syncwarp();
            // A2 fragments for the k=8 slice
            uint32_t e0 = __float_as_uint(Ht[g * 12 + tig]);
            uint32_t e1 = __float_as_uint(Ht[(g + 8) * 12 + tig]);
            uint32_t e2 = __float_as_uint(Ht[g * 12 + tig + 4]);
            uint32_t e3 = __float_as_uint(Ht[(g + 8) * 12 + tig + 4]);
            uint32_t e4 = __float_as_uint(Ht[(g + 16) * 12 + tig]);
            uint32_t e5 = __float_as_uint(Ht[(g + 24) * 12 + tig]);
            uint32_t e6 = __float_as_uint(Ht[(g + 16) * 12 + tig + 4]);
            uint32_t e7 = __float_as_uint(Ht[(g + 24) * 12 + tig + 4]);
            __syncwarp();
            // MMA2: H3 += H2slice x W3c[nt*8.., :]
            #pragma unroll
            for (int mt = 0; mt < 13; ++mt) {
                uint32_t b0 = __float_as_uint(sm[W3C_ + (nt * 8 + tig) * 104 + mt * 8 + g]);
                uint32_t b1 = __float_as_uint(sm[W3C_ + (nt * 8 + tig + 4) * 104 + mt * 8 + g]);
                mma8(h3[mt][0], h3[mt][1], h3[mt][2], h3[mt][3], e0, e1, e2, e3, b0, b1);
                mma8(h3[mt][4], h3[mt][5], h3[mt][6], h3[mt][7], e4, e5, e6, e7, b0, b1);
            }
        }
    }

    // ---- layer 4: per-thread partials, quad butterfly, scatter ----
    float p[4][6];
    #pragma unroll
    for (int ri = 0; ri < 4; ++ri)
        #pragma unroll
        for (int o = 0; o < 6; ++o) p[ri][o] = 0.0f;

    #pragma unroll
    for (int mt = 0; mt < 13; ++mt) {
        #pragma unroll
        for (int q = 0; q < 8; ++q) {
            int m = mt * 8 + 2 * tig + (q & 1);
            int ri = ((q >> 1) & 1) + 2 * (q >> 2);
            if (m < 100) {
                float h = fmaxf(h3[mt][q] + sm[SB3_ + m], 0.0f);
                #pragma unroll
                for (int o = 0; o < 6; ++o)
                    p[ri][o] = fmaf(h, sm[SW4_ + m * 6 + o], p[ri][o]);
            }
        }
    }
    #pragma unroll
    for (int ri = 0; ri < 4; ++ri)
        #pragma unroll
        for (int o = 0; o < 6; ++o) {
            p[ri][o] += __shfl_xor_sync(0xffffffffu, p[ri][o], 1);
            p[ri][o] += __shfl_xor_sync(0xffffffffu, p[ri][o], 2);
        }

    // lane scatters sample row = g + 8*tig
    const int row = g + 8 * tig;
    const int gidx = base + w * 32 + row;
    if (gidx < cnt) {
        const int s = g_perm[a * NB + gidx];
        float pr[6];
        #pragma unroll
        for (int o = 0; o < 6; ++o) pr[o] = p[tig][o] + sm[SB4_ + o];
        float att2[6];
        #pragma unroll
        for (int k = 0; k < 6; ++k) att2[k] = g_att[s * 6 + k];
        const int ptr = g_ptr[s];
        int idxs[6];
        idxs[0] = 0;
        idxs[1] = ptr;
        idxs[2] = clampi(ptr - GS);
        idxs[3] = clampi(ptr + GS);
        idxs[4] = clampi(ptr - 1);
        idxs[5] = clampi(ptr + 1);
        float* orow = out + (size_t)s * XDIM;
        #pragma unroll
        for (int j = 0; j < 6; ++j) orow[idxs[j]] = att2[j] + pr[j];
    }
}

// ---------- launch ----------
extern "C" void kernel_launch(void* const* d_in, const int* in_sizes, int n_in,
                              void* d_out, int out_size) {
    const float* x  = (const float*)d_in[0];
    const float* W1 = (const float*)d_in[1];
    const float* b1 = (const float*)d_in[2];
    const float* W2 = (const float*)d_in[3];
    const float* b2 = (const float*)d_in[4];
    const float* W3 = (const float*)d_in[5];
    const float* b3 = (const float*)d_in[6];
    const float* W4 = (const float*)d_in[7];
    const float* b4 = (const float*)d_in[8];
    const int* act  = (const int*)d_in[9];
    float* out = (float*)d_out;

    static void* cnt_addr = nullptr;
    if (!cnt_addr) cudaGetSymbolAddress(&cnt_addr, g_cnt);
    static bool attr_done = false;
    if (!attr_done) {
        cudaFuncSetAttribute(k_mlp, cudaFuncAttributeMaxDynamicSharedMemorySize, SMEMB);
        attr_done = true;
    }

    cudaMemsetAsync(cnt_addr, 0, NACT * sizeof(int));
    k_prep<<<NB / 8, 256>>>(x, act, out);
    dim3 g2((NB + 127) / 128, NACT);
    k_mlp<<<g2, 128, SMEMB>>>(W1, b1, W2, b2, W3, b3, W4, b4, out);
}

// round 6
// speedup vs baseline: 2.2595x; 1.6642x over previous
#include <cuda_runtime.h>
#include <cstdint>

#define NB 65536
#define XDIM 362
#define NACT 3
#define GS 19

// ---------- scratch ----------
__device__ int   g_cnt[NACT];
__device__ int   g_perm[NACT * NB];
__device__ int   g_ptr[NB];
__device__ float g_att[NB * 6];

__device__ __forceinline__ int clampi(int v) { return min(max(v, 1), XDIM - 1); }

__device__ __forceinline__ uint32_t to_tf32(float f) {
    uint32_t r;
    asm("cvt.rna.tf32.f32 %0, %1;" : "=r"(r) : "f"(f));
    return r;
}
__device__ __forceinline__ float tf32f(float f) {
    return __uint_as_float(to_tf32(f));
}
// D += A(16x8) * B(8x8), tf32 inputs, f32 accum
__device__ __forceinline__ void mma8(float& c0, float& c1, float& c2, float& c3,
                                     uint32_t a0, uint32_t a1, uint32_t a2, uint32_t a3,
                                     uint32_t b0, uint32_t b1) {
    asm volatile(
        "mma.sync.aligned.m16n8k8.row.col.f32.tf32.tf32.f32 "
        "{%0,%1,%2,%3}, {%4,%5,%6,%7}, {%8,%9}, {%0,%1,%2,%3};"
        : "+f"(c0), "+f"(c1), "+f"(c2), "+f"(c3)
        : "r"(a0), "r"(a1), "r"(a2), "r"(a3), "r"(b0), "r"(b1));
}
// permuted column position within an 8-block: [0,4,1,5,2,6,3,7]
__device__ __forceinline__ int cperm(int r) { return (r < 4) ? 2 * r : 2 * (r - 4) + 1; }

// ---------- K1: argmax + copy + gather + action bucketing ----------
__global__ void __launch_bounds__(256) k_prep(const float* __restrict__ x,
                                              const int* __restrict__ act,
                                              float* __restrict__ out) {
    const int warp = threadIdx.x >> 5;
    const int lane = threadIdx.x & 31;
    const int row = blockIdx.x * 8 + warp;

    const float2* __restrict__ xr = (const float2*)(x + (size_t)row * XDIM);
    float2* __restrict__ orow = (float2*)(out + (size_t)row * XDIM);

    float bv = -3.4e38f;
    int bi = 0;
    #pragma unroll
    for (int it = 0; it < 6; ++it) {
        int i = it * 32 + lane;
        if (i < 181) {
            float2 v = xr[i];
            orow[i] = v;
            int c0 = 2 * i;
            if (v.x > bv) { bv = v.x; bi = c0; }
            if (v.y > bv) { bv = v.y; bi = c0 + 1; }
        }
    }
    #pragma unroll
    for (int off = 16; off; off >>= 1) {
        float ov = __shfl_down_sync(0xffffffffu, bv, off);
        int oi = __shfl_down_sync(0xffffffffu, bi, off);
        if (ov > bv || (ov == bv && oi < bi)) { bv = ov; bi = oi; }
    }
    const int ptr = __shfl_sync(0xffffffffu, bi, 0);

    if (lane < 6) {
        int idx;
        if (lane == 0) idx = 0;
        else if (lane == 1) idx = ptr;
        else if (lane == 2) idx = clampi(ptr - GS);
        else if (lane == 3) idx = clampi(ptr + GS);
        else if (lane == 4) idx = clampi(ptr - 1);
        else idx = clampi(ptr + 1);
        g_att[row * 6 + lane] = x[(size_t)row * XDIM + idx];
    }
    if (lane == 0) {
        g_ptr[row] = ptr;
        int a = act[row];
        int pos = atomicAdd(&g_cnt[a], 1);
        g_perm[a * NB + pos] = row;
    }
}

// ---------- K2: mma.sync tf32 MLP, 8 warps / 256 samples per CTA ----------
// smem float offsets
#define W2C_ 0            // [104 k][104 n] tf32
#define W3C_ 10816        // [104 j][104 m] tf32
#define HB1_ 21632        // per-warp H1 [32][104], permuted cols
#define HT_  48256        // per-warp Htmp [32][24], permuted cols
#define SW1_ 54400        // W1 [6][100]
#define SB1_ 55000
#define SB2_ 55100
#define SB3_ 55500
#define SW4_ 55600        // W4 [100][6]
#define SB4_ 56200
#define SMEMF 56208
#define SMEMB (SMEMF * 4)
#define NW 8
#define CTAS 256          // samples per CTA

__global__ void __launch_bounds__(NW * 32, 1) k_mlp(
    const float* __restrict__ W1, const float* __restrict__ b1,
    const float* __restrict__ W2, const float* __restrict__ b2,
    const float* __restrict__ W3, const float* __restrict__ b3,
    const float* __restrict__ W4, const float* __restrict__ b4,
    float* __restrict__ out)
{
    extern __shared__ float sm[];
    const int a = blockIdx.y;
    const int cnt = g_cnt[a];
    const int base = blockIdx.x * CTAS;
    if (base >= cnt) return;
    const int tid = threadIdx.x;
    const int w = tid >> 5;
    const int lane = tid & 31;
    const int g = lane >> 2;       // groupID (row group)
    const int tig = lane & 3;      // thread in group

    float* __restrict__ Hw = sm + HB1_ + w * (32 * 104);
    float* __restrict__ Ht = sm + HT_ + w * (32 * 24);
    const float* __restrict__ W2g = W2 + a * 40000;
    const float* __restrict__ W3g = W3 + a * 40000;

    // small weights
    for (int t = tid; t < 600; t += NW * 32) sm[SW1_ + t] = W1[a * 600 + t];
    for (int t = tid; t < 100; t += NW * 32) sm[SB1_ + t] = b1[a * 100 + t];
    for (int t = tid; t < 400; t += NW * 32) sm[SB2_ + t] = b2[a * 400 + t];
    for (int t = tid; t < 100; t += NW * 32) sm[SB3_ + t] = b3[a * 100 + t];
    for (int t = tid; t < 600; t += NW * 32) sm[SW4_ + t] = W4[a * 600 + t];
    for (int t = tid; t < 8; t += NW * 32) sm[SB4_ + t] = (t < 6) ? b4[a * 6 + t] : 0.0f;

    // ---- layer 1: one lane = one sample, write tf32 H1 (permuted cols) ----
    {
        const int gidx = base + w * 32 + lane;
        const bool act_s = gidx < cnt;
        const int s = g_perm[a * NB + (act_s ? gidx : 0)];
        float att[6];
        #pragma unroll
        for (int k = 0; k < 6; ++k) att[k] = g_att[s * 6 + k];
        for (int m = 0; m < 104; ++m) {
            float v = 0.0f;
            if (m < 100) {
                float acc = sm[SB1_ + m];
                #pragma unroll
                for (int k = 0; k < 6; ++k) acc = fmaf(att[k], sm[SW1_ + k * 100 + m], acc);
                v = tf32f(fmaxf(acc, 0.0f));
            }
            Hw[lane * 104 + (m & ~7) + cperm(m & 7)] = v;
        }
    }

    // H3 accumulators: [13 m-tiles][8]
    float h3[13][8];
    #pragma unroll
    for (int mt = 0; mt < 13; ++mt)
        #pragma unroll
        for (int q = 0; q < 8; ++q) h3[mt][q] = 0.0f;

    // ---- chunks of 100 j's ----
    #pragma unroll 1
    for (int c = 0; c < 4; ++c) {
        __syncthreads();
        const int cb = c * 100;
        for (int t = tid; t < 10816; t += NW * 32) {
            int k = t / 104, n = t - k * 104;
            bool ok = (k < 100) && (n < 100);
            sm[W2C_ + t] = ok ? tf32f(W2g[k * 400 + cb + n]) : 0.0f;
            sm[W3C_ + t] = ok ? tf32f(W3g[(cb + k) * 100 + n]) : 0.0f;
        }
        __syncthreads();

        #pragma unroll 1
        for (int nt = 0; nt < 13; ++nt) {
            // MMA1: d = H1[32 x 104] x W2c[:, nt*8..nt*8+7]
            float d[8];
            #pragma unroll
            for (int q = 0; q < 8; ++q) d[q] = 0.0f;
            #pragma unroll
            for (int k = 0; k < 13; ++k) {
                const int k0 = k * 8;
                float2 f02 = *(const float2*)(Hw + g * 104 + k0 + 2 * tig);
                float2 f13 = *(const float2*)(Hw + (g + 8) * 104 + k0 + 2 * tig);
                float2 f46 = *(const float2*)(Hw + (g + 16) * 104 + k0 + 2 * tig);
                float2 f57 = *(const float2*)(Hw + (g + 24) * 104 + k0 + 2 * tig);
                uint32_t b0 = __float_as_uint(sm[W2C_ + (k0 + tig) * 104 + nt * 8 + g]);
                uint32_t b1 = __float_as_uint(sm[W2C_ + (k0 + tig + 4) * 104 + nt * 8 + g]);
                mma8(d[0], d[1], d[2], d[3],
                     __float_as_uint(f02.x), __float_as_uint(f13.x),
                     __float_as_uint(f02.y), __float_as_uint(f13.y), b0, b1);
                mma8(d[4], d[5], d[6], d[7],
                     __float_as_uint(f46.x), __float_as_uint(f57.x),
                     __float_as_uint(f46.y), __float_as_uint(f57.y), b0, b1);
            }
            // bias + relu + tf32, store k=8 slice to Htmp (permuted cols)
            {
                const int jl = nt * 8 + 2 * tig;
                float bb0 = 0.0f, bb1 = 0.0f;
                bool okj = jl < 100;
                if (okj) { bb0 = sm[SB2_ + cb + jl]; bb1 = sm[SB2_ + cb + jl + 1]; }
                float v0 = okj ? fmaxf(d[0] + bb0, 0.0f) : 0.0f;
                float v1 = okj ? fmaxf(d[1] + bb1, 0.0f) : 0.0f;
                float v2 = okj ? fmaxf(d[2] + bb0, 0.0f) : 0.0f;
                float v3 = okj ? fmaxf(d[3] + bb1, 0.0f) : 0.0f;
                float v4 = okj ? fmaxf(d[4] + bb0, 0.0f) : 0.0f;
                float v5 = okj ? fmaxf(d[5] + bb1, 0.0f) : 0.0f;
                float v6 = okj ? fmaxf(d[6] + bb0, 0.0f) : 0.0f;
                float v7 = okj ? fmaxf(d[7] + bb1, 0.0f) : 0.0f;
                const int p0 = cperm(2 * tig);
                const int p1 = cperm(2 * tig + 1);
                Ht[g * 24 + p0] = tf32f(v0);
                Ht[g * 24 + p1] = tf32f(v1);
                Ht[(g + 8) * 24 + p0] = tf32f(v2);
                Ht[(g + 8) * 24 + p1] = tf32f(v3);
                Ht[(g + 16) * 24 + p0] = tf32f(v4);
                Ht[(g + 16) * 24 + p1] = tf32f(v5);
                Ht[(g + 24) * 24 + p0] = tf32f(v6);
                Ht[(g + 24) * 24 + p1] = tf32f(v7);
            }
            __syncwarp();
            // A2 fragments: LDS.64 pairs {col tig, col tig+4}
            float2 e02 = *(const float2*)(Ht + g * 24 + 2 * tig);
            float2 e13 = *(const float2*)(Ht + (g + 8) * 24 + 2 * tig);
            float2 e46 = *(const float2*)(Ht + (g + 16) * 24 + 2 * tig);
            float2 e57 = *(const float2*)(Ht + (g + 24) * 24 + 2 * tig);
            __syncwarp();
            uint32_t e0 = __float_as_uint(e02.x), e2 = __float_as_uint(e02.y);
            uint32_t e1 = __float_as_uint(e13.x), e3 = __float_as_uint(e13.y);
            uint32_t e4 = __float_as_uint(e46.x), e6 = __float_as_uint(e46.y);
            uint32_t e5 = __float_as_uint(e57.x), e7 = __float_as_uint(e57.y);
            // MMA2: H3 += H2slice x W3c[nt*8.., :]
            #pragma unroll
            for (int mt = 0; mt < 13; ++mt) {
                uint32_t b0 = __float_as_uint(sm[W3C_ + (nt * 8 + tig) * 104 + mt * 8 + g]);
                uint32_t b1 = __float_as_uint(sm[W3C_ + (nt * 8 + tig + 4) * 104 + mt * 8 + g]);
                mma8(h3[mt][0], h3[mt][1], h3[mt][2], h3[mt][3], e0, e1, e2, e3, b0, b1);
                mma8(h3[mt][4], h3[mt][5], h3[mt][6], h3[mt][7], e4, e5, e6, e7, b0, b1);
            }
        }
    }

    // ---- layer 4: per-thread partials, quad butterfly, scatter ----
    float p[4][6];
    #pragma unroll
    for (int ri = 0; ri < 4; ++ri)
        #pragma unroll
        for (int o = 0; o < 6; ++o) p[ri][o] = 0.0f;

    #pragma unroll
    for (int mt = 0; mt < 13; ++mt) {
        #pragma unroll
        for (int q = 0; q < 8; ++q) {
            int m = mt * 8 + 2 * tig + (q & 1);
            int ri = ((q >> 1) & 1) + 2 * (q >> 2);
            if (m < 100) {
                float h = fmaxf(h3[mt][q] + sm[SB3_ + m], 0.0f);
                #pragma unroll
                for (int o = 0; o < 6; ++o)
                    p[ri][o] = fmaf(h, sm[SW4_ + m * 6 + o], p[ri][o]);
            }
        }
    }
    #pragma unroll
    for (int ri = 0; ri < 4; ++ri)
        #pragma unroll
        for (int o = 0; o < 6; ++o) {
            p[ri][o] += __shfl_xor_sync(0xffffffffu, p[ri][o], 1);
            p[ri][o] += __shfl_xor_sync(0xffffffffu, p[ri][o], 2);
        }

    // lane scatters sample row = g + 8*tig
    const int row = g + 8 * tig;
    const int gidx = base + w * 32 + row;
    if (gidx < cnt) {
        const int s = g_perm[a * NB + gidx];
        float pr[6];
        #pragma unroll
        for (int o = 0; o < 6; ++o) pr[o] = p[tig][o] + sm[SB4_ + o];
        float att2[6];
        #pragma unroll
        for (int k = 0; k < 6; ++k) att2[k] = g_att[s * 6 + k];
        const int ptr = g_ptr[s];
        int idxs[6];
        idxs[0] = 0;
        idxs[1] = ptr;
        idxs[2] = clampi(ptr - GS);
        idxs[3] = clampi(ptr + GS);
        idxs[4] = clampi(ptr - 1);
        idxs[5] = clampi(ptr + 1);
        float* orow = out + (size_t)s * XDIM;
        #pragma unroll
        for (int j = 0; j < 6; ++j) orow[idxs[j]] = att2[j] + pr[j];
    }
}

// ---------- launch ----------
extern "C" void kernel_launch(void* const* d_in, const int* in_sizes, int n_in,
                              void* d_out, int out_size) {
    const float* x  = (const float*)d_in[0];
    const float* W1 = (const float*)d_in[1];
    const float* b1 = (const float*)d_in[2];
    const float* W2 = (const float*)d_in[3];
    const float* b2 = (const float*)d_in[4];
    const float* W3 = (const float*)d_in[5];
    const float* b3 = (const float*)d_in[6];
    const float* W4 = (const float*)d_in[7];
    const float* b4 = (const float*)d_in[8];
    const int* act  = (const int*)d_in[9];
    float* out = (float*)d_out;

    static void* cnt_addr = nullptr;
    if (!cnt_addr) cudaGetSymbolAddress(&cnt_addr, g_cnt);
    static bool attr_done = false;
    if (!attr_done) {
        cudaFuncSetAttribute(k_mlp, cudaFuncAttributeMaxDynamicSharedMemorySize, SMEMB);
        attr_done = true;
    }

    cudaMemsetAsync(cnt_addr, 0, NACT * sizeof(int));
    k_prep<<<NB / 8, 256>>>(x, act, out);
    dim3 g2((NB + CTAS - 1) / CTAS, NACT);
    k_mlp<<<g2, NW * 32, SMEMB>>>(W1, b1, W2, b2, W3, b3, W4, b4, out);
}